// round 2
// baseline (speedup 1.0000x reference)
#include <cuda_runtime.h>
#include <cuda_bf16.h>
#include <math_constants.h>

#define NN 50000
#define NE 800000
#define FIN 24
#define HD 128
#define NG 100
#define TWO_H 256

// ---------------- scratch (static __device__, no allocation) ----------------
__device__ __align__(16) float g_PQ[NN * TWO_H];   // per-node [p | q]
__device__ __align__(16) float g_h[NN * HD];       // layer activations
__device__ int   g_deg[NN];
__device__ int   g_row[NN + 1];
__device__ int   g_cur[NN];
__device__ int   g_csrc[NE];
__device__ float g_Wc[HD * TWO_H];      // combined weight [K][256]
__device__ float g_sums[2 * HD];        // BN sum | sumsq
__device__ float g_scale[HD];
__device__ float g_shift[HD];
__device__ float g_gsum[NG * HD];
__device__ float g_gcnt[NG];

// ---------------- init ----------------
__global__ void k_zero_init() {
    int i = blockIdx.x * blockDim.x + threadIdx.x;
    if (i < NN) g_deg[i] = 0;
    if (i < NG * HD) g_gsum[i] = 0.f;
    if (i < NG) g_gcnt[i] = 0.f;
}

__global__ void k_hist(const int* __restrict__ dst) {
    int e = blockIdx.x * blockDim.x + threadIdx.x;
    if (e < NE) atomicAdd(&g_deg[dst[e]], 1);
}

__global__ void k_scan() {
    __shared__ int buf[1024];
    __shared__ int s_carry;
    if (threadIdx.x == 0) s_carry = 0;
    __syncthreads();
    int nchunks = (NN + 1023) / 1024;
    for (int c = 0; c < nchunks; c++) {
        int i = c * 1024 + threadIdx.x;
        int v = (i < NN) ? g_deg[i] : 0;
        buf[threadIdx.x] = v;
        __syncthreads();
        for (int off = 1; off < 1024; off <<= 1) {
            int t = (threadIdx.x >= off) ? buf[threadIdx.x - off] : 0;
            __syncthreads();
            buf[threadIdx.x] += t;
            __syncthreads();
        }
        int incl = buf[threadIdx.x];
        int ex = s_carry + incl - v;
        if (i < NN) { g_row[i] = ex; g_cur[i] = ex; }
        __syncthreads();
        if (threadIdx.x == 0) s_carry += buf[1023];
        __syncthreads();
    }
    if (threadIdx.x == 0) g_row[NN] = s_carry;
}

__global__ void k_scatter(const int* __restrict__ src, const int* __restrict__ dst) {
    int e = blockIdx.x * blockDim.x + threadIdx.x;
    if (e < NE) {
        int d = dst[e];
        int pos = atomicAdd(&g_cur[d], 1);
        g_csrc[pos] = src[e];
    }
}

// ---------------- weight prep: Wc[k][j] = Wt-Wb, Wc[k][128+j] = Wb ----------
__global__ void k_prepw(const float* __restrict__ W, int K) {
    int tid = blockIdx.x * blockDim.x + threadIdx.x;
    if (tid < 2 * HD) g_sums[tid] = 0.f;
    int total = K * HD;
    for (int i = tid; i < total; i += gridDim.x * blockDim.x) {
        int k = i / HD, j = i % HD;
        float wt = W[k * HD + j];
        float wb = W[(K + k) * HD + j];
        g_Wc[k * TWO_H + j] = wt - wb;
        g_Wc[k * TWO_H + HD + j] = wb;
    }
}

// ---------------- SGEMM: g_PQ = act(A) @ g_Wc (+bias on first 128 cols) -----
// use_h=1 -> A = g_h (device symbol, resolved IN DEVICE CODE) with BN+relu applied
#define BM 64
#define BN 64
#define BK 16
__global__ void k_gemm(const float* __restrict__ A_ext, int K,
                       const float* __restrict__ bias, int use_h) {
    const float* A = use_h ? g_h : A_ext;
    __shared__ float As[BK][BM];
    __shared__ float Bs[BK][BN];
    int bm = blockIdx.x * BM;
    int bn = blockIdx.y * BN;
    int tid = threadIdx.x;
    int tx = tid & 15, ty = tid >> 4;
    float acc[4][4] = {};
    for (int k0 = 0; k0 < K; k0 += BK) {
        #pragma unroll
        for (int e = 0; e < 4; e++) {
            int idx = e * 256 + tid;
            int ml = idx / BK, kl = idx % BK;
            int gm = bm + ml, gk = k0 + kl;
            float v = 0.f;
            if (gm < NN && gk < K) {
                v = A[gm * K + gk];
                if (use_h) v = fmaxf(0.f, fmaf(g_scale[gk], v, g_shift[gk]));
            }
            As[kl][ml] = v;
        }
        #pragma unroll
        for (int e = 0; e < 4; e++) {
            int idx = e * 256 + tid;
            int kl = idx / BN, nl = idx % BN;
            int gk = k0 + kl;
            Bs[kl][nl] = (gk < K) ? g_Wc[gk * TWO_H + bn + nl] : 0.f;
        }
        __syncthreads();
        #pragma unroll
        for (int kk = 0; kk < BK; kk++) {
            float4 a4 = *(const float4*)&As[kk][ty * 4];
            float4 b4 = *(const float4*)&Bs[kk][tx * 4];
            float a[4] = {a4.x, a4.y, a4.z, a4.w};
            float b[4] = {b4.x, b4.y, b4.z, b4.w};
            #pragma unroll
            for (int i = 0; i < 4; i++)
                #pragma unroll
                for (int j = 0; j < 4; j++)
                    acc[i][j] = fmaf(a[i], b[j], acc[i][j]);
        }
        __syncthreads();
    }
    #pragma unroll
    for (int i = 0; i < 4; i++) {
        int gm = bm + ty * 4 + i;
        if (gm >= NN) continue;
        #pragma unroll
        for (int j = 0; j < 4; j++) {
            int gn = bn + tx * 4 + j;
            float v = acc[i][j];
            if (gn < HD) v += bias[gn];
            g_PQ[gm * TWO_H + gn] = v;
        }
    }
}

// ---------------- edge max + relu + BN-stats ----------------
__global__ void k_edgemax() {
    __shared__ float s_acc[2 * HD];
    for (int t = threadIdx.x; t < 2 * HD; t += blockDim.x) s_acc[t] = 0.f;
    __syncthreads();
    int gwarp = (blockIdx.x * blockDim.x + threadIdx.x) >> 5;
    int lane = threadIdx.x & 31;
    int nwarps = (gridDim.x * blockDim.x) >> 5;
    const float4* PQ4 = (const float4*)g_PQ;   // node stride = 64 float4
    float4* h4 = (float4*)g_h;                 // node stride = 32 float4
    float lsum[4] = {0, 0, 0, 0};
    float lsq[4] = {0, 0, 0, 0};
    for (int i = gwarp; i < NN; i += nwarps) {
        float4 p = PQ4[i * 64 + lane];
        int s0 = g_row[i], s1 = g_row[i + 1];
        float4 mx = make_float4(-CUDART_INF_F, -CUDART_INF_F, -CUDART_INF_F, -CUDART_INF_F);
        for (int e = s0; e < s1; e++) {
            int s = g_csrc[e];
            float4 q = PQ4[s * 64 + 32 + lane];
            mx.x = fmaxf(mx.x, q.x); mx.y = fmaxf(mx.y, q.y);
            mx.z = fmaxf(mx.z, q.z); mx.w = fmaxf(mx.w, q.w);
        }
        float4 hv;
        if (s1 == s0) {
            hv = make_float4(0.f, 0.f, 0.f, 0.f);
        } else {
            hv.x = fmaxf(0.f, p.x + mx.x);
            hv.y = fmaxf(0.f, p.y + mx.y);
            hv.z = fmaxf(0.f, p.z + mx.z);
            hv.w = fmaxf(0.f, p.w + mx.w);
        }
        h4[i * 32 + lane] = hv;
        lsum[0] += hv.x; lsum[1] += hv.y; lsum[2] += hv.z; lsum[3] += hv.w;
        lsq[0] += hv.x * hv.x; lsq[1] += hv.y * hv.y;
        lsq[2] += hv.z * hv.z; lsq[3] += hv.w * hv.w;
    }
    #pragma unroll
    for (int c = 0; c < 4; c++) {
        atomicAdd(&s_acc[lane * 4 + c], lsum[c]);
        atomicAdd(&s_acc[HD + lane * 4 + c], lsq[c]);
    }
    __syncthreads();
    for (int t = threadIdx.x; t < 2 * HD; t += blockDim.x)
        atomicAdd(&g_sums[t], s_acc[t]);
}

// ---------------- BN finalize -> affine scale/shift ----------------
__global__ void k_bnfin(const float* __restrict__ gamma, const float* __restrict__ beta) {
    int f = threadIdx.x;
    if (f >= HD) return;
    float inv_n = 1.0f / (float)NN;
    float mu = g_sums[f] * inv_n;
    float var = g_sums[HD + f] * inv_n - mu * mu;
    float sc = gamma[f] / sqrtf(var + 1e-5f);
    g_scale[f] = sc;
    g_shift[f] = beta[f] - mu * sc;
}

// ---------------- pooling accumulate (batch sorted/contiguous) --------------
__global__ void k_pool(const int* __restrict__ batch) {
    int t = threadIdx.x;   // feature, 128 threads
    int n0 = blockIdx.x * 256;
    int n1 = min(n0 + 256, NN);
    float acc = 0.f;
    int cnt = 0;
    int curg = -1;
    for (int n = n0; n < n1; n++) {
        int g = batch[n];
        if (g != curg) {
            if (curg >= 0) {
                atomicAdd(&g_gsum[curg * HD + t], acc);
                if (t == 0) atomicAdd(&g_gcnt[curg], (float)cnt);
            }
            curg = g; acc = 0.f; cnt = 0;
        }
        acc += g_h[n * HD + t];
        cnt++;
    }
    if (curg >= 0) {
        atomicAdd(&g_gsum[curg * HD + t], acc);
        if (t == 0) atomicAdd(&g_gcnt[curg], (float)cnt);
    }
}

// ---------------- final: BN3-apply + mean + linear + relu -------------------
__global__ void k_final(const float* __restrict__ Wl, const float* __restrict__ bl,
                        float* __restrict__ out) {
    __shared__ float red[HD];
    int g = blockIdx.x;
    int t = threadIdx.x;
    float c = g_gcnt[g];
    float pooled;
    if (c > 0.f)
        pooled = g_scale[t] * g_gsum[g * HD + t] / c + g_shift[t];
    else
        pooled = 0.f;
    red[t] = pooled * Wl[t];
    __syncthreads();
    for (int off = 64; off > 0; off >>= 1) {
        if (t < off) red[t] += red[t + off];
        __syncthreads();
    }
    if (t == 0) out[g] = fmaxf(0.f, red[0] + bl[0]);
}

// ---------------- launch ----------------
extern "C" void kernel_launch(void* const* d_in, const int* in_sizes, int n_in,
                              void* d_out, int out_size) {
    const float* x  = (const float*)d_in[0];
    const int* ei   = (const int*)d_in[1];
    const int* batch = (const int*)d_in[2];
    const float* W1 = (const float*)d_in[3];
    const float* b1 = (const float*)d_in[4];
    const float* W2 = (const float*)d_in[5];
    const float* b2 = (const float*)d_in[6];
    const float* W3 = (const float*)d_in[7];
    const float* b3 = (const float*)d_in[8];
    const float* g1 = (const float*)d_in[9];
    const float* be1 = (const float*)d_in[10];
    const float* g2 = (const float*)d_in[11];
    const float* be2 = (const float*)d_in[12];
    const float* g3 = (const float*)d_in[13];
    const float* be3 = (const float*)d_in[14];
    const float* Wl = (const float*)d_in[15];
    const float* bl = (const float*)d_in[16];
    float* out = (float*)d_out;

    const int* src = ei;
    const int* dst = ei + NE;

    // CSR build
    k_zero_init<<<(NN + 255) / 256, 256>>>();
    k_hist<<<(NE + 255) / 256, 256>>>(dst);
    k_scan<<<1, 1024>>>();
    k_scatter<<<(NE + 255) / 256, 256>>>(src, dst);

    dim3 ggrid((NN + BM - 1) / BM, TWO_H / BN);

    // layer 1
    k_prepw<<<32, 256>>>(W1, FIN);
    k_gemm<<<ggrid, 256>>>(x, FIN, b1, 0);
    k_edgemax<<<512, 256>>>();
    k_bnfin<<<1, 128>>>(g1, be1);

    // layer 2
    k_prepw<<<32, 256>>>(W2, HD);
    k_gemm<<<ggrid, 256>>>(nullptr, HD, b2, 1);
    k_edgemax<<<512, 256>>>();
    k_bnfin<<<1, 128>>>(g2, be2);

    // layer 3
    k_prepw<<<32, 256>>>(W3, HD);
    k_gemm<<<ggrid, 256>>>(nullptr, HD, b3, 1);
    k_edgemax<<<512, 256>>>();
    k_bnfin<<<1, 128>>>(g3, be3);

    // pool + final
    k_pool<<<(NN + 255) / 256, 128>>>(batch);
    k_final<<<NG, 128>>>(Wl, bl, out);
}

// round 3
// speedup vs baseline: 1.1517x; 1.1517x over previous
#include <cuda_runtime.h>
#include <cuda_bf16.h>
#include <math_constants.h>

#define NN 50000
#define NE 800000
#define FIN 24
#define HD 128
#define NG 100
#define TWO_H 256

// ---------------- scratch (static __device__, no allocation) ----------------
__device__ __align__(16) float g_PQ[NN * TWO_H];   // per-node [p | q]
__device__ __align__(16) float g_h[NN * HD];       // layer activations
__device__ int   g_deg[NN];
__device__ int   g_row[NN + 1];
__device__ int   g_cur[NN];
__device__ int   g_csrc[NE];
__device__ float g_sums[2 * HD];        // BN sum | sumsq (reset by finalize)
__device__ __align__(16) float g_scale[HD];
__device__ __align__(16) float g_shift[HD];
__device__ float g_gsum[NG * HD];
__device__ float g_gcnt[NG];
__device__ int   g_ctr;                 // edgemax finalize counter (reset by finalize)

// ---------------- init ----------------
__global__ void k_zero_init() {
    int i = blockIdx.x * blockDim.x + threadIdx.x;
    if (i < NN) g_deg[i] = 0;
    if (i < NG * HD) g_gsum[i] = 0.f;
    if (i < NG) g_gcnt[i] = 0.f;
}

__global__ void k_hist(const int* __restrict__ dst) {
    int e4 = blockIdx.x * blockDim.x + threadIdx.x;
    if (e4 < NE / 4) {
        int4 d = ((const int4*)dst)[e4];
        atomicAdd(&g_deg[d.x], 1);
        atomicAdd(&g_deg[d.y], 1);
        atomicAdd(&g_deg[d.z], 1);
        atomicAdd(&g_deg[d.w], 1);
    }
}

// two-phase scan: 1 block, 1024 threads, each owns a contiguous chunk
__global__ void k_scan() {
    __shared__ int ssum[1024];
    const int CH = (NN + 1023) / 1024;   // 49
    int t = threadIdx.x;
    int base = t * CH;
    int local = 0;
    for (int i = 0; i < CH; i++) {
        int idx = base + i;
        if (idx < NN) local += g_deg[idx];
    }
    ssum[t] = local;
    __syncthreads();
    for (int off = 1; off < 1024; off <<= 1) {
        int v = (t >= off) ? ssum[t - off] : 0;
        __syncthreads();
        ssum[t] += v;
        __syncthreads();
    }
    int run = ssum[t] - local;   // exclusive prefix
    for (int i = 0; i < CH; i++) {
        int idx = base + i;
        if (idx < NN) {
            g_row[idx] = run;
            g_cur[idx] = run;
            run += g_deg[idx];
        }
    }
    if (t == 1023) g_row[NN] = ssum[1023];
}

__global__ void k_scatter(const int* __restrict__ src, const int* __restrict__ dst) {
    int e = blockIdx.x * blockDim.x + threadIdx.x;
    if (e < NE) {
        int d = dst[e];
        int pos = atomicAdd(&g_cur[d], 1);
        g_csrc[pos] = src[e];
    }
}

// ---------------- SGEMM: g_PQ = act(A) @ [Wt-Wb | Wb] (+bias on p half) -----
// B built on-the-fly from raw W [2K,H]. use_h=1 -> A=g_h with BN+relu fused.
#define BM 128
#define BK 16
__global__ __launch_bounds__(256) void k_gemm(const float* __restrict__ A_ext, int K,
                                              const float* __restrict__ W,
                                              const float* __restrict__ bias, int use_h) {
    const float* A = use_h ? g_h : A_ext;
    __shared__ float As[BK][BM];
    __shared__ float Bs[BK][HD];
    int bm = blockIdx.x * BM;
    int isP = (blockIdx.y == 0);   // cols 0..127 = p-part (Wt-Wb, +bias); else q-part (Wb)
    int tid = threadIdx.x;
    int tx = tid & 15, ty = tid >> 4;
    float acc[8][8] = {};
    int a_ch = tid & 3;        // float4 chunk within BK
    int a_row = tid >> 2;      // 0..63
    int b_c4 = tid & 31;       // 0..31 (float4 col)
    int b_kr = tid >> 5;       // 0..7

    for (int k0 = 0; k0 < K; k0 += BK) {
        // ---- load A tile (128 x 16), transposed into As[k][m]
        #pragma unroll
        for (int h = 0; h < 2; h++) {
            int ml = a_row + h * 64;
            int gm = bm + ml;
            int gk = k0 + a_ch * 4;
            float4 v = make_float4(0.f, 0.f, 0.f, 0.f);
            if (gm < NN && gk < K) {
                v = *(const float4*)&A[gm * K + gk];
                if (use_h) {
                    float4 sc = *(const float4*)&g_scale[gk];
                    float4 sh = *(const float4*)&g_shift[gk];
                    v.x = fmaxf(0.f, fmaf(sc.x, v.x, sh.x));
                    v.y = fmaxf(0.f, fmaf(sc.y, v.y, sh.y));
                    v.z = fmaxf(0.f, fmaf(sc.z, v.z, sh.z));
                    v.w = fmaxf(0.f, fmaf(sc.w, v.w, sh.w));
                }
            }
            As[a_ch * 4 + 0][ml] = v.x;
            As[a_ch * 4 + 1][ml] = v.y;
            As[a_ch * 4 + 2][ml] = v.z;
            As[a_ch * 4 + 3][ml] = v.w;
        }
        // ---- load B tile (16 x 128) from W, combined on the fly
        #pragma unroll
        for (int h = 0; h < 2; h++) {
            int kl = b_kr + h * 8;
            int gk = k0 + kl;
            int nl = b_c4 * 4;
            float4 v = make_float4(0.f, 0.f, 0.f, 0.f);
            if (gk < K) {
                float4 wb = *(const float4*)&W[(K + gk) * HD + nl];
                if (isP) {
                    float4 wt = *(const float4*)&W[gk * HD + nl];
                    v.x = wt.x - wb.x; v.y = wt.y - wb.y;
                    v.z = wt.z - wb.z; v.w = wt.w - wb.w;
                } else {
                    v = wb;
                }
            }
            *(float4*)&Bs[kl][nl] = v;
        }
        __syncthreads();
        #pragma unroll
        for (int kk = 0; kk < BK; kk++) {
            float rA[8], rB[8];
            *(float4*)&rA[0] = *(const float4*)&As[kk][ty * 8];
            *(float4*)&rA[4] = *(const float4*)&As[kk][ty * 8 + 4];
            *(float4*)&rB[0] = *(const float4*)&Bs[kk][tx * 8];
            *(float4*)&rB[4] = *(const float4*)&Bs[kk][tx * 8 + 4];
            #pragma unroll
            for (int i = 0; i < 8; i++)
                #pragma unroll
                for (int j = 0; j < 8; j++)
                    acc[i][j] = fmaf(rA[i], rB[j], acc[i][j]);
        }
        __syncthreads();
    }
    // ---- epilogue
    int colbase = (isP ? 0 : HD) + tx * 8;
    float bv[8];
    #pragma unroll
    for (int j = 0; j < 8; j++) bv[j] = isP ? bias[tx * 8 + j] : 0.f;
    #pragma unroll
    for (int i = 0; i < 8; i++) {
        int gm = bm + ty * 8 + i;
        if (gm >= NN) continue;
        float4 o0 = make_float4(acc[i][0] + bv[0], acc[i][1] + bv[1],
                                acc[i][2] + bv[2], acc[i][3] + bv[3]);
        float4 o1 = make_float4(acc[i][4] + bv[4], acc[i][5] + bv[5],
                                acc[i][6] + bv[6], acc[i][7] + bv[7]);
        *(float4*)&g_PQ[gm * TWO_H + colbase] = o0;
        *(float4*)&g_PQ[gm * TWO_H + colbase + 4] = o1;
    }
}

// ---------------- edge max + relu + BN-stats + fused BN finalize ------------
__global__ void k_edgemax(const float* __restrict__ gamma, const float* __restrict__ beta) {
    __shared__ float s_acc[2 * HD];
    for (int t = threadIdx.x; t < 2 * HD; t += blockDim.x) s_acc[t] = 0.f;
    __syncthreads();
    int gwarp = (blockIdx.x * blockDim.x + threadIdx.x) >> 5;
    int lane = threadIdx.x & 31;
    int nwarps = (gridDim.x * blockDim.x) >> 5;
    const float4* PQ4 = (const float4*)g_PQ;   // node stride = 64 float4
    float4* h4 = (float4*)g_h;                 // node stride = 32 float4
    float lsum[4] = {0, 0, 0, 0};
    float lsq[4] = {0, 0, 0, 0};
    for (int i = gwarp; i < NN; i += nwarps) {
        float4 p = PQ4[i * 64 + lane];
        int s0 = g_row[i], s1 = g_row[i + 1];
        float4 mx = make_float4(-CUDART_INF_F, -CUDART_INF_F, -CUDART_INF_F, -CUDART_INF_F);
        int e = s0;
        for (; e + 1 < s1; e += 2) {
            int sa = g_csrc[e], sb = g_csrc[e + 1];
            float4 qa = PQ4[sa * 64 + 32 + lane];
            float4 qb = PQ4[sb * 64 + 32 + lane];
            mx.x = fmaxf(mx.x, fmaxf(qa.x, qb.x));
            mx.y = fmaxf(mx.y, fmaxf(qa.y, qb.y));
            mx.z = fmaxf(mx.z, fmaxf(qa.z, qb.z));
            mx.w = fmaxf(mx.w, fmaxf(qa.w, qb.w));
        }
        if (e < s1) {
            int sa = g_csrc[e];
            float4 qa = PQ4[sa * 64 + 32 + lane];
            mx.x = fmaxf(mx.x, qa.x); mx.y = fmaxf(mx.y, qa.y);
            mx.z = fmaxf(mx.z, qa.z); mx.w = fmaxf(mx.w, qa.w);
        }
        float4 hv;
        if (s1 == s0) {
            hv = make_float4(0.f, 0.f, 0.f, 0.f);
        } else {
            hv.x = fmaxf(0.f, p.x + mx.x);
            hv.y = fmaxf(0.f, p.y + mx.y);
            hv.z = fmaxf(0.f, p.z + mx.z);
            hv.w = fmaxf(0.f, p.w + mx.w);
        }
        h4[i * 32 + lane] = hv;
        lsum[0] += hv.x; lsum[1] += hv.y; lsum[2] += hv.z; lsum[3] += hv.w;
        lsq[0] += hv.x * hv.x; lsq[1] += hv.y * hv.y;
        lsq[2] += hv.z * hv.z; lsq[3] += hv.w * hv.w;
    }
    #pragma unroll
    for (int c = 0; c < 4; c++) {
        atomicAdd(&s_acc[lane * 4 + c], lsum[c]);
        atomicAdd(&s_acc[HD + lane * 4 + c], lsq[c]);
    }
    __syncthreads();
    for (int t = threadIdx.x; t < 2 * HD; t += blockDim.x)
        atomicAdd(&g_sums[t], s_acc[t]);

    // ---- last-block BN finalize: scale/shift + reset for next layer
    __threadfence();
    __shared__ int is_last;
    if (threadIdx.x == 0)
        is_last = (atomicAdd(&g_ctr, 1) == (int)gridDim.x - 1);
    __syncthreads();
    if (is_last) {
        int f = threadIdx.x;
        if (f < HD) {
            float inv_n = 1.0f / (float)NN;
            float mu = g_sums[f] * inv_n;
            float var = g_sums[HD + f] * inv_n - mu * mu;
            float sc = gamma[f] / sqrtf(var + 1e-5f);
            g_scale[f] = sc;
            g_shift[f] = beta[f] - mu * sc;
            g_sums[f] = 0.f;
            g_sums[HD + f] = 0.f;
        }
        if (f == 0) g_ctr = 0;
    }
}

// ---------------- pooling accumulate (batch contiguous) ---------------------
__global__ void k_pool(const int* __restrict__ batch) {
    int t = threadIdx.x;   // feature, 128 threads
    int n0 = blockIdx.x * 256;
    int n1 = min(n0 + 256, NN);
    float acc = 0.f;
    int cnt = 0;
    int curg = -1;
    for (int n = n0; n < n1; n++) {
        int g = batch[n];
        if (g != curg) {
            if (curg >= 0) {
                atomicAdd(&g_gsum[curg * HD + t], acc);
                if (t == 0) atomicAdd(&g_gcnt[curg], (float)cnt);
            }
            curg = g; acc = 0.f; cnt = 0;
        }
        acc += g_h[n * HD + t];
        cnt++;
    }
    if (curg >= 0) {
        atomicAdd(&g_gsum[curg * HD + t], acc);
        if (t == 0) atomicAdd(&g_gcnt[curg], (float)cnt);
    }
}

// ---------------- final: BN3-apply + mean + linear + relu -------------------
__global__ void k_final(const float* __restrict__ Wl, const float* __restrict__ bl,
                        float* __restrict__ out) {
    __shared__ float red[HD];
    int g = blockIdx.x;
    int t = threadIdx.x;
    float c = g_gcnt[g];
    float pooled;
    if (c > 0.f)
        pooled = g_scale[t] * g_gsum[g * HD + t] / c + g_shift[t];
    else
        pooled = 0.f;
    red[t] = pooled * Wl[t];
    __syncthreads();
    for (int off = 64; off > 0; off >>= 1) {
        if (t < off) red[t] += red[t + off];
        __syncthreads();
    }
    if (t == 0) out[g] = fmaxf(0.f, red[0] + bl[0]);
}

// ---------------- launch ----------------
extern "C" void kernel_launch(void* const* d_in, const int* in_sizes, int n_in,
                              void* d_out, int out_size) {
    const float* x  = (const float*)d_in[0];
    const int* ei   = (const int*)d_in[1];
    const int* batch = (const int*)d_in[2];
    const float* W1 = (const float*)d_in[3];
    const float* b1 = (const float*)d_in[4];
    const float* W2 = (const float*)d_in[5];
    const float* b2 = (const float*)d_in[6];
    const float* W3 = (const float*)d_in[7];
    const float* b3 = (const float*)d_in[8];
    const float* g1 = (const float*)d_in[9];
    const float* be1 = (const float*)d_in[10];
    const float* g2 = (const float*)d_in[11];
    const float* be2 = (const float*)d_in[12];
    const float* g3 = (const float*)d_in[13];
    const float* be3 = (const float*)d_in[14];
    const float* Wl = (const float*)d_in[15];
    const float* bl = (const float*)d_in[16];
    float* out = (float*)d_out;

    const int* src = ei;
    const int* dst = ei + NE;

    // CSR build
    k_zero_init<<<(NN + 255) / 256, 256>>>();
    k_hist<<<(NE / 4 + 255) / 256, 256>>>(dst);
    k_scan<<<1, 1024>>>();
    k_scatter<<<(NE + 255) / 256, 256>>>(src, dst);

    dim3 ggrid((NN + BM - 1) / BM, 2);

    // layer 1
    k_gemm<<<ggrid, 256>>>(x, FIN, W1, b1, 0);
    k_edgemax<<<512, 256>>>(g1, be1);

    // layer 2
    k_gemm<<<ggrid, 256>>>(nullptr, HD, W2, b2, 1);
    k_edgemax<<<512, 256>>>(g2, be2);

    // layer 3
    k_gemm<<<ggrid, 256>>>(nullptr, HD, W3, b3, 1);
    k_edgemax<<<512, 256>>>(g3, be3);

    // pool + final
    k_pool<<<(NN + 255) / 256, 128>>>(batch);
    k_final<<<NG, 128>>>(Wl, bl, out);
}

// round 5
// speedup vs baseline: 1.3964x; 1.2125x over previous
#include <cuda_runtime.h>
#include <cuda_bf16.h>
#include <math_constants.h>
#include <cstdint>

#define NN 50000
#define NE 800000
#define FIN 24
#define HD 128
#define NG 100
#define TWO_H 256

// ---------------- scratch (static __device__, no allocation) ----------------
__device__ __align__(16) float g_PQ[NN * TWO_H];   // per-node [p | q]
__device__ __align__(16) float g_h[NN * HD];       // layer activations
__device__ int   g_deg[NN];
__device__ int   g_row[NN + 1];
__device__ int   g_cur[NN];
__device__ int   g_csrc[NE];
__device__ float g_sums[2 * HD];
__device__ __align__(16) float g_scale[HD];
__device__ __align__(16) float g_shift[HD];
__device__ float g_gsum[NG * HD];
__device__ float g_gcnt[NG];
__device__ int   g_ctr;
// split combined-weight images: [half][k][n], n=0..127, k<K
__device__ __align__(16) unsigned short g_Bhi[2 * 128 * 128];
__device__ __align__(16) unsigned short g_Blo[2 * 128 * 128];

// ---------------- helpers ----------------
__device__ __forceinline__ uint32_t smem_u32(const void* p) {
    uint32_t a;
    asm("{ .reg .u64 t; cvta.to.shared.u64 t, %1; cvt.u32.u64 %0, t; }" : "=r"(a) : "l"(p));
    return a;
}
__device__ __forceinline__ void ldmx4(uint32_t* r, uint32_t addr) {
    asm volatile("ldmatrix.sync.aligned.m8n8.x4.shared.b16 {%0,%1,%2,%3}, [%4];"
                 : "=r"(r[0]), "=r"(r[1]), "=r"(r[2]), "=r"(r[3]) : "r"(addr));
}
__device__ __forceinline__ void ldmx4t(uint32_t* r, uint32_t addr) {
    asm volatile("ldmatrix.sync.aligned.m8n8.x4.trans.shared.b16 {%0,%1,%2,%3}, [%4];"
                 : "=r"(r[0]), "=r"(r[1]), "=r"(r[2]), "=r"(r[3]) : "r"(addr));
}
__device__ __forceinline__ void mma16816(float* d, const uint32_t* a, uint32_t b0, uint32_t b1) {
    asm volatile("mma.sync.aligned.m16n8k16.row.col.f32.bf16.bf16.f32 "
                 "{%0,%1,%2,%3},{%4,%5,%6,%7},{%8,%9},{%0,%1,%2,%3};"
                 : "+f"(d[0]), "+f"(d[1]), "+f"(d[2]), "+f"(d[3])
                 : "r"(a[0]), "r"(a[1]), "r"(a[2]), "r"(a[3]), "r"(b0), "r"(b1));
}
__device__ __forceinline__ unsigned short bf16bits(float v) {
    __nv_bfloat16 h = __float2bfloat16(v);
    return reinterpret_cast<unsigned short&>(h);
}

// ---------------- init / CSR ----------------
__global__ void k_zero_init() {
    int i = blockIdx.x * blockDim.x + threadIdx.x;
    if (i < NN) g_deg[i] = 0;
    if (i < NG * HD) g_gsum[i] = 0.f;
    if (i < NG) g_gcnt[i] = 0.f;
}

__global__ void k_hist(const int* __restrict__ dst) {
    int e4 = blockIdx.x * blockDim.x + threadIdx.x;
    if (e4 < NE / 4) {
        int4 d = ((const int4*)dst)[e4];
        atomicAdd(&g_deg[d.x], 1);
        atomicAdd(&g_deg[d.y], 1);
        atomicAdd(&g_deg[d.z], 1);
        atomicAdd(&g_deg[d.w], 1);
    }
}

__global__ void k_scan() {
    __shared__ int ssum[1024];
    const int CH = (NN + 1023) / 1024;
    int t = threadIdx.x;
    int base = t * CH;
    int local = 0;
    for (int i = 0; i < CH; i++) {
        int idx = base + i;
        if (idx < NN) local += g_deg[idx];
    }
    ssum[t] = local;
    __syncthreads();
    for (int off = 1; off < 1024; off <<= 1) {
        int v = (t >= off) ? ssum[t - off] : 0;
        __syncthreads();
        ssum[t] += v;
        __syncthreads();
    }
    int run = ssum[t] - local;
    for (int i = 0; i < CH; i++) {
        int idx = base + i;
        if (idx < NN) {
            g_row[idx] = run;
            g_cur[idx] = run;
            run += g_deg[idx];
        }
    }
    if (t == 1023) g_row[NN] = ssum[1023];
}

__global__ void k_scatter(const int* __restrict__ src, const int* __restrict__ dst) {
    int e = blockIdx.x * blockDim.x + threadIdx.x;
    if (e < NE) {
        int d = dst[e];
        int pos = atomicAdd(&g_cur[d], 1);
        g_csrc[pos] = src[e];
    }
}

// ------------- B prep: combined weight -> split hi/lo bf16 images -----------
// half 0: Wt - Wb (p part); half 1: Wb (q part). layout [half][k][n]
template<int K>
__global__ void k_prepB(const float* __restrict__ W) {
    int idx = blockIdx.x * blockDim.x + threadIdx.x;
    if (idx >= 2 * K * HD) return;
    int half = idx / (K * HD);
    int rem = idx % (K * HD);
    int k = rem / HD, n = rem % HD;
    float v;
    if (half == 0) v = W[k * HD + n] - W[(K + k) * HD + n];
    else           v = W[(K + k) * HD + n];
    __nv_bfloat16 h = __float2bfloat16(v);
    unsigned short hb = reinterpret_cast<unsigned short&>(h);
    unsigned short lb = bf16bits(v - __bfloat162float(h));
    g_Bhi[(half * K + k) * HD + n] = hb;
    g_Blo[(half * K + k) * HD + n] = lb;
}

// ------------- mma.sync GEMM: g_PQ half = act(A) @ Bc, bf16x3 split ---------
// CTA: 128 rows x 128 cols, 8 warps (warp tile 32x64). Full K in SMEM.
template<int K, int KP, int USE_H>
__global__ __launch_bounds__(256) void k_gemm_mma(const float* __restrict__ A_ext,
                                                  const float* __restrict__ bias) {
    const int SA = KP + 8;     // A smem stride (bf16)
    const int SB = 136;        // B smem stride (bf16)
    extern __shared__ __align__(16) unsigned short sh[];
    unsigned short* Ah = sh;
    unsigned short* Al = Ah + 128 * SA;
    unsigned short* Bh = Al + 128 * SA;
    unsigned short* Bl = Bh + KP * SB;

    const float* A = USE_H ? g_h : A_ext;
    int tid = threadIdx.x, lane = tid & 31, wid = tid >> 5;
    int wm = wid >> 1, wn = wid & 1;
    int bm = blockIdx.x * 128;
    int half = blockIdx.y;

    // ---- stage A: fp32 load (+BN/relu), hi/lo split, padded store
    for (int idx = tid; idx < 128 * (KP / 2); idx += 256) {
        int r = idx / (KP / 2);
        int c = (idx % (KP / 2)) * 2;
        int gm = bm + r;
        float2 v = make_float2(0.f, 0.f);
        if (gm < NN && c < K) {
            v = *(const float2*)&A[gm * K + c];
            if (USE_H) {
                float2 sc = *(const float2*)&g_scale[c];
                float2 shf = *(const float2*)&g_shift[c];
                v.x = fmaxf(0.f, fmaf(sc.x, v.x, shf.x));
                v.y = fmaxf(0.f, fmaf(sc.y, v.y, shf.y));
            }
        }
        __nv_bfloat16 hx = __float2bfloat16(v.x);
        __nv_bfloat16 hy = __float2bfloat16(v.y);
        unsigned short hxb = reinterpret_cast<unsigned short&>(hx);
        unsigned short hyb = reinterpret_cast<unsigned short&>(hy);
        unsigned short lxb = bf16bits(v.x - __bfloat162float(hx));
        unsigned short lyb = bf16bits(v.y - __bfloat162float(hy));
        *(uint32_t*)&Ah[r * SA + c] = (uint32_t)hxb | ((uint32_t)hyb << 16);
        *(uint32_t*)&Al[r * SA + c] = (uint32_t)lxb | ((uint32_t)lyb << 16);
    }
    // ---- stage B: copy split images (8 bf16 chunks), zero-pad k >= K
    for (int idx = tid; idx < KP * 16; idx += 256) {
        int k = idx >> 4, ch = idx & 15;
        float4 vh = make_float4(0.f, 0.f, 0.f, 0.f), vl = vh;
        if (k < K) {
            vh = ((const float4*)g_Bhi)[(half * K + k) * 16 + ch];
            vl = ((const float4*)g_Blo)[(half * K + k) * 16 + ch];
        }
        *(float4*)&Bh[k * SB + ch * 8] = vh;
        *(float4*)&Bl[k * SB + ch * 8] = vl;
    }
    __syncthreads();

    // ---- compute
    float acc[2][8][4];
    #pragma unroll
    for (int i = 0; i < 2; i++)
        #pragma unroll
        for (int j = 0; j < 8; j++)
            #pragma unroll
            for (int c = 0; c < 4; c++) acc[i][j][c] = 0.f;

    uint32_t aRowOff = ((uint32_t)(wm * 32 + (lane & 15)) * SA + ((lane >> 4) & 1) * 8) * 2;
    uint32_t aH = smem_u32(Ah) + aRowOff;
    uint32_t aL = smem_u32(Al) + aRowOff;
    uint32_t bRowOff = ((uint32_t)((lane & 7) + ((lane >> 3) & 1) * 8) * SB
                        + wn * 64 + ((lane >> 4) & 1) * 8) * 2;
    uint32_t bH = smem_u32(Bh) + bRowOff;
    uint32_t bL = smem_u32(Bl) + bRowOff;

    #pragma unroll
    for (int ks = 0; ks < KP / 16; ks++) {
        uint32_t ah[2][4], al[2][4];
        #pragma unroll
        for (int i = 0; i < 2; i++) {
            ldmx4(ah[i], aH + (uint32_t)(i * 16 * SA + ks * 16) * 2);
            ldmx4(al[i], aL + (uint32_t)(i * 16 * SA + ks * 16) * 2);
        }
        #pragma unroll
        for (int g = 0; g < 4; g++) {
            uint32_t bh[4], bl[4];
            uint32_t off = (uint32_t)(ks * 16 * SB + g * 16) * 2;
            ldmx4t(bh, bH + off);
            ldmx4t(bl, bL + off);
            #pragma unroll
            for (int s = 0; s < 2; s++) {
                int j = g * 2 + s;
                #pragma unroll
                for (int i = 0; i < 2; i++) {
                    mma16816(acc[i][j], ah[i], bh[s * 2], bh[s * 2 + 1]);
                    mma16816(acc[i][j], al[i], bh[s * 2], bh[s * 2 + 1]);
                    mma16816(acc[i][j], ah[i], bl[s * 2], bl[s * 2 + 1]);
                }
            }
        }
    }

    // ---- epilogue: write g_PQ half, bias on p-half
    int rbase = bm + wm * 32 + (lane >> 2);
    #pragma unroll
    for (int i = 0; i < 2; i++) {
        int gm0 = rbase + i * 16;
        int gm1 = gm0 + 8;
        #pragma unroll
        for (int j = 0; j < 8; j++) {
            int coll = wn * 64 + j * 8 + (lane & 3) * 2;
            int col = half * HD + coll;
            float bx = 0.f, by = 0.f;
            if (half == 0) { bx = bias[coll]; by = bias[coll + 1]; }
            if (gm0 < NN) {
                float2 o = make_float2(acc[i][j][0] + bx, acc[i][j][1] + by);
                *(float2*)&g_PQ[gm0 * TWO_H + col] = o;
            }
            if (gm1 < NN) {
                float2 o = make_float2(acc[i][j][2] + bx, acc[i][j][3] + by);
                *(float2*)&g_PQ[gm1 * TWO_H + col] = o;
            }
        }
    }
}

// ---------------- edge max + relu + BN-stats + fused BN finalize ------------
__global__ void k_edgemax(const float* __restrict__ gamma, const float* __restrict__ beta) {
    __shared__ float s_acc[2 * HD];
    for (int t = threadIdx.x; t < 2 * HD; t += blockDim.x) s_acc[t] = 0.f;
    __syncthreads();
    int gwarp = (blockIdx.x * blockDim.x + threadIdx.x) >> 5;
    int lane = threadIdx.x & 31;
    int nwarps = (gridDim.x * blockDim.x) >> 5;
    const float4* PQ4 = (const float4*)g_PQ;
    float4* h4 = (float4*)g_h;
    float lsum[4] = {0, 0, 0, 0};
    float lsq[4] = {0, 0, 0, 0};
    for (int i = gwarp; i < NN; i += nwarps) {
        float4 p = PQ4[i * 64 + lane];
        int s0 = g_row[i], s1 = g_row[i + 1];
        float4 mx = make_float4(-CUDART_INF_F, -CUDART_INF_F, -CUDART_INF_F, -CUDART_INF_F);
        int e = s0;
        for (; e + 1 < s1; e += 2) {
            int sa = g_csrc[e], sb = g_csrc[e + 1];
            float4 qa = PQ4[sa * 64 + 32 + lane];
            float4 qb = PQ4[sb * 64 + 32 + lane];
            mx.x = fmaxf(mx.x, fmaxf(qa.x, qb.x));
            mx.y = fmaxf(mx.y, fmaxf(qa.y, qb.y));
            mx.z = fmaxf(mx.z, fmaxf(qa.z, qb.z));
            mx.w = fmaxf(mx.w, fmaxf(qa.w, qb.w));
        }
        if (e < s1) {
            int sa = g_csrc[e];
            float4 qa = PQ4[sa * 64 + 32 + lane];
            mx.x = fmaxf(mx.x, qa.x); mx.y = fmaxf(mx.y, qa.y);
            mx.z = fmaxf(mx.z, qa.z); mx.w = fmaxf(mx.w, qa.w);
        }
        float4 hv;
        if (s1 == s0) {
            hv = make_float4(0.f, 0.f, 0.f, 0.f);
        } else {
            hv.x = fmaxf(0.f, p.x + mx.x);
            hv.y = fmaxf(0.f, p.y + mx.y);
            hv.z = fmaxf(0.f, p.z + mx.z);
            hv.w = fmaxf(0.f, p.w + mx.w);
        }
        h4[i * 32 + lane] = hv;
        lsum[0] += hv.x; lsum[1] += hv.y; lsum[2] += hv.z; lsum[3] += hv.w;
        lsq[0] += hv.x * hv.x; lsq[1] += hv.y * hv.y;
        lsq[2] += hv.z * hv.z; lsq[3] += hv.w * hv.w;
    }
    #pragma unroll
    for (int c = 0; c < 4; c++) {
        atomicAdd(&s_acc[lane * 4 + c], lsum[c]);
        atomicAdd(&s_acc[HD + lane * 4 + c], lsq[c]);
    }
    __syncthreads();
    for (int t = threadIdx.x; t < 2 * HD; t += blockDim.x)
        atomicAdd(&g_sums[t], s_acc[t]);

    __threadfence();
    __shared__ int is_last;
    if (threadIdx.x == 0)
        is_last = (atomicAdd(&g_ctr, 1) == (int)gridDim.x - 1);
    __syncthreads();
    if (is_last) {
        int f = threadIdx.x;
        if (f < HD) {
            float inv_n = 1.0f / (float)NN;
            float mu = g_sums[f] * inv_n;
            float var = g_sums[HD + f] * inv_n - mu * mu;
            float sc = gamma[f] / sqrtf(var + 1e-5f);
            g_scale[f] = sc;
            g_shift[f] = beta[f] - mu * sc;
            g_sums[f] = 0.f;
            g_sums[HD + f] = 0.f;
        }
        if (f == 0) g_ctr = 0;
    }
}

// ---------------- pooling + final ----------------
__global__ void k_pool(const int* __restrict__ batch) {
    int t = threadIdx.x;
    int n0 = blockIdx.x * 256;
    int n1 = min(n0 + 256, NN);
    float acc = 0.f;
    int cnt = 0;
    int curg = -1;
    for (int n = n0; n < n1; n++) {
        int g = batch[n];
        if (g != curg) {
            if (curg >= 0) {
                atomicAdd(&g_gsum[curg * HD + t], acc);
                if (t == 0) atomicAdd(&g_gcnt[curg], (float)cnt);
            }
            curg = g; acc = 0.f; cnt = 0;
        }
        acc += g_h[n * HD + t];
        cnt++;
    }
    if (curg >= 0) {
        atomicAdd(&g_gsum[curg * HD + t], acc);
        if (t == 0) atomicAdd(&g_gcnt[curg], (float)cnt);
    }
}

__global__ void k_final(const float* __restrict__ Wl, const float* __restrict__ bl,
                        float* __restrict__ out) {
    __shared__ float red[HD];
    int g = blockIdx.x;
    int t = threadIdx.x;
    float c = g_gcnt[g];
    float pooled;
    if (c > 0.f)
        pooled = g_scale[t] * g_gsum[g * HD + t] / c + g_shift[t];
    else
        pooled = 0.f;
    red[t] = pooled * Wl[t];
    __syncthreads();
    for (int off = 64; off > 0; off >>= 1) {
        if (t < off) red[t] += red[t + off];
        __syncthreads();
    }
    if (t == 0) out[g] = fmaxf(0.f, red[0] + bl[0]);
}

// ---------------- launch ----------------
extern "C" void kernel_launch(void* const* d_in, const int* in_sizes, int n_in,
                              void* d_out, int out_size) {
    const float* x  = (const float*)d_in[0];
    const int* ei   = (const int*)d_in[1];
    const int* batch = (const int*)d_in[2];
    const float* W1 = (const float*)d_in[3];
    const float* b1 = (const float*)d_in[4];
    const float* W2 = (const float*)d_in[5];
    const float* b2 = (const float*)d_in[6];
    const float* W3 = (const float*)d_in[7];
    const float* b3 = (const float*)d_in[8];
    const float* g1 = (const float*)d_in[9];
    const float* be1 = (const float*)d_in[10];
    const float* g2 = (const float*)d_in[11];
    const float* be2 = (const float*)d_in[12];
    const float* g3 = (const float*)d_in[13];
    const float* be3 = (const float*)d_in[14];
    const float* Wl = (const float*)d_in[15];
    const float* bl = (const float*)d_in[16];
    float* out = (float*)d_out;

    const int* src = ei;
    const int* dst = ei + NE;

    // smem sizes (bytes): A hi/lo [128][KP+8] + B hi/lo [KP][136], bf16
    const int SM1 = (2 * 128 * (32 + 8) + 2 * 32 * 136) * 2;     // 37888
    const int SM2 = (2 * 128 * (128 + 8) + 2 * 128 * 136) * 2;   // 139264
    static int attr_done = 0;
    if (!attr_done) {
        cudaFuncSetAttribute(k_gemm_mma<FIN, 32, 0>, cudaFuncAttributeMaxDynamicSharedMemorySize, SM1);
        cudaFuncSetAttribute(k_gemm_mma<HD, 128, 1>, cudaFuncAttributeMaxDynamicSharedMemorySize, SM2);
        attr_done = 1;
    }

    // CSR build
    k_zero_init<<<(NN + 255) / 256, 256>>>();
    k_hist<<<(NE / 4 + 255) / 256, 256>>>(dst);
    k_scan<<<1, 1024>>>();
    k_scatter<<<(NE + 255) / 256, 256>>>(src, dst);

    dim3 ggrid((NN + 127) / 128, 2);

    // layer 1
    k_prepB<FIN><<<(2 * FIN * HD + 255) / 256, 256>>>(W1);
    k_gemm_mma<FIN, 32, 0><<<ggrid, 256, SM1>>>(x, b1);
    k_edgemax<<<512, 256>>>(g1, be1);

    // layer 2
    k_prepB<HD><<<(2 * HD * HD + 255) / 256, 256>>>(W2);
    k_gemm_mma<HD, 128, 1><<<ggrid, 256, SM2>>>(nullptr, b2);
    k_edgemax<<<512, 256>>>(g2, be2);

    // layer 3
    k_prepB<HD><<<(2 * HD * HD + 255) / 256, 256>>>(W3);
    k_gemm_mma<HD, 128, 1><<<ggrid, 256, SM2>>>(nullptr, b3);
    k_edgemax<<<512, 256>>>(g3, be3);

    // pool + final
    k_pool<<<(NN + 255) / 256, 128>>>(batch);
    k_final<<<NG, 128>>>(Wl, bl, out);
}